// round 3
// baseline (speedup 1.0000x reference)
#include <cuda_runtime.h>
#include <cstdint>

// Problem constants
#define B_Q   256
#define DIM   512
#define N_MEM 500000
#define TOPK  5

// Tiling
#define BN         64
#define KC         16
#define NCHUNK     (DIM / KC)            // 32
#define SPLIT_ROWS 512
#define TILES      (SPLIT_ROWS / BN)     // 8
#define NSPLIT     ((N_MEM + SPLIT_ROWS - 1) / SPLIT_ROWS)  // 977

// Dynamic smem layout (floats):
//  As: KC*256 = 4096 | Bs2: KC*128 = 2048 (duplicated pairs) | ds: 256*65 = 16640
//  qs: 256 | ms: 64 | bd: 1280 | bi(int): 1280
#define SMEM_FLOATS (KC*256 + KC*128 + 256*65 + 256 + BN + B_Q*TOPK)
#define SMEM_BYTES  ((SMEM_FLOATS + B_Q*TOPK) * 4)

// Scratch (device globals: no allocation allowed)
__device__ float g_qsq[B_Q];
__device__ float g_pd[(size_t)B_Q * NSPLIT * TOPK];
__device__ int   g_pi[(size_t)B_Q * NSPLIT * TOPK];

__device__ __forceinline__ void fma_f32x2(unsigned long long& acc,
                                          unsigned long long a,
                                          unsigned long long b) {
    asm("fma.rn.f32x2 %0, %1, %2, %0;" : "+l"(acc) : "l"(a), "l"(b));
}

// ---------------------------------------------------------------------------
// Query sum-of-squares: one warp per row
// ---------------------------------------------------------------------------
__global__ void qsq_kernel(const float* __restrict__ qm) {
    int w    = (blockIdx.x * blockDim.x + threadIdx.x) >> 5;
    int lane = threadIdx.x & 31;
    if (w >= B_Q) return;
    const float4* row = (const float4*)(qm + (long)w * DIM);
    float s = 0.f;
#pragma unroll
    for (int i = 0; i < 4; i++) {
        float4 v = row[lane + 32 * i];
        s += v.x * v.x + v.y * v.y + v.z * v.z + v.w * v.w;
    }
#pragma unroll
    for (int o = 16; o > 0; o >>= 1) s += __shfl_xor_sync(0xFFFFFFFFu, s, o);
    if (lane == 0) g_qsq[w] = s;
}

// ---------------------------------------------------------------------------
// Main: 256x64 distance tiles, packed f32x2 FMA, fused m_sq + running top-5.
// ---------------------------------------------------------------------------
__global__ void __launch_bounds__(256, 1)
knn_main(const float* __restrict__ qm, const float* __restrict__ mem) {
    extern __shared__ float sm[];
    float* As  = sm;                     // [KC][256]   k-major A (queries)
    float* Bs2 = As + KC * 256;          // [KC][128]   k-major B, each value duplicated {b,b}
    float* ds  = Bs2 + KC * 128;         // [256][65]   distance tile
    float* qs  = ds + 256 * 65;          // [256]
    float* ms  = qs + 256;               // [64]
    float* bd  = ms + BN;                // [256][5]
    int*   bi  = (int*)(bd + B_Q * TOPK);

    const int tid = threadIdx.x;
    const int tm  = tid & 31;   // m-group lane
    const int tn  = tid >> 5;   // n-group (warp id) -> B loads warp-uniform

    qs[tid] = g_qsq[tid];
#pragma unroll
    for (int j = 0; j < TOPK; j++) { bd[tid * TOPK + j] = 3.0e38f; bi[tid * TOPK + j] = 0; }
    __syncthreads();

    const int splitBase = blockIdx.x * SPLIT_ROWS;
    const float4* qrow  = (const float4*)(qm + (long)tid * DIM);
    const int br = tid >> 2;    // B tile row 0..63
    const int bk = tid & 3;     // float4 slot within 16-float k-chunk

    for (int tile = 0; tile < TILES; tile++) {
        const int n0    = splitBase + tile * BN;
        const int gr    = n0 + br;
        const bool bval = (gr < N_MEM);
        const float4* mrow = (const float4*)(mem + (long)(bval ? gr : 0) * DIM);

        unsigned long long acc2[4][8];
#pragma unroll
        for (int ip = 0; ip < 4; ip++)
#pragma unroll
            for (int j = 0; j < 8; j++) acc2[ip][j] = 0ULL;

        float rsq = 0.f;   // partial ||m_br||^2 over this thread's k-slots

        float4 ra0 = qrow[0], ra1 = qrow[1], ra2 = qrow[2], ra3 = qrow[3];
        float4 rb  = bval ? mrow[bk] : make_float4(0.f, 0.f, 0.f, 0.f);

        for (int c = 0; c < NCHUNK; c++) {
            // stage A (k-major)
            As[0 * 256 + tid]  = ra0.x; As[1 * 256 + tid]  = ra0.y;
            As[2 * 256 + tid]  = ra0.z; As[3 * 256 + tid]  = ra0.w;
            As[4 * 256 + tid]  = ra1.x; As[5 * 256 + tid]  = ra1.y;
            As[6 * 256 + tid]  = ra1.z; As[7 * 256 + tid]  = ra1.w;
            As[8 * 256 + tid]  = ra2.x; As[9 * 256 + tid]  = ra2.y;
            As[10 * 256 + tid] = ra2.z; As[11 * 256 + tid] = ra2.w;
            As[12 * 256 + tid] = ra3.x; As[13 * 256 + tid] = ra3.y;
            As[14 * 256 + tid] = ra3.z; As[15 * 256 + tid] = ra3.w;
            // stage B duplicated pairs {b,b}
            *(float2*)(Bs2 + (bk * 4 + 0) * 128 + 2 * br) = make_float2(rb.x, rb.x);
            *(float2*)(Bs2 + (bk * 4 + 1) * 128 + 2 * br) = make_float2(rb.y, rb.y);
            *(float2*)(Bs2 + (bk * 4 + 2) * 128 + 2 * br) = make_float2(rb.z, rb.z);
            *(float2*)(Bs2 + (bk * 4 + 3) * 128 + 2 * br) = make_float2(rb.w, rb.w);
            rsq += rb.x * rb.x + rb.y * rb.y + rb.z * rb.z + rb.w * rb.w;
            __syncthreads();

            if (c + 1 < NCHUNK) {
                int k4 = (c + 1) * 4;
                ra0 = qrow[k4 + 0]; ra1 = qrow[k4 + 1];
                ra2 = qrow[k4 + 2]; ra3 = qrow[k4 + 3];
                rb  = bval ? mrow[k4 + bk] : make_float4(0.f, 0.f, 0.f, 0.f);
            }

#pragma unroll
            for (int kk = 0; kk < KC; kk++) {
                // A pairs: natural adjacency in k-major row
                ulonglong2 A0 = *(const ulonglong2*)(As + kk * 256 + tm * 4);
                ulonglong2 A1 = *(const ulonglong2*)(As + kk * 256 + 128 + tm * 4);
                // B pairs: duplicated layout, warp-uniform broadcast loads
                const float* brow = Bs2 + kk * 128;
                ulonglong2 B0 = *(const ulonglong2*)(brow + tn * 8);
                ulonglong2 B1 = *(const ulonglong2*)(brow + tn * 8 + 4);
                ulonglong2 B2 = *(const ulonglong2*)(brow + 64 + tn * 8);
                ulonglong2 B3 = *(const ulonglong2*)(brow + 64 + tn * 8 + 4);
                unsigned long long ap[4] = {A0.x, A0.y, A1.x, A1.y};
                unsigned long long bp[8] = {B0.x, B0.y, B1.x, B1.y,
                                            B2.x, B2.y, B3.x, B3.y};
#pragma unroll
                for (int ip = 0; ip < 4; ip++)
#pragma unroll
                    for (int j = 0; j < 8; j++)
                        fma_f32x2(acc2[ip][j], ap[ip], bp[j]);
            }
            __syncthreads();
        }

        // reduce ||m||^2 across the 4 bk lanes (consecutive lanes in warp)
        {
            float s = rsq;
            s += __shfl_xor_sync(0xFFFFFFFFu, s, 1);
            s += __shfl_xor_sync(0xFFFFFFFFu, s, 2);
            if (bk == 0) ms[br] = bval ? s : 3.0e38f;
        }
        __syncthreads();

        // distances into smem tile
#pragma unroll
        for (int ip = 0; ip < 4; ip++) {
            int m0 = (ip < 2) ? (tm * 4 + 2 * ip) : (128 + tm * 4 + 2 * (ip - 2));
            float q0 = qs[m0], q1 = qs[m0 + 1];
#pragma unroll
            for (int j = 0; j < 8; j++) {
                int n = (j < 4) ? (tn * 4 + j) : (32 + tn * 4 + (j - 4));
                float2 v = *(float2*)&acc2[ip][j];
                float mn = ms[n];
                ds[m0 * 65 + n]       = q0 + mn - 2.0f * v.x;
                ds[(m0 + 1) * 65 + n] = q1 + mn - 2.0f * v.y;
            }
        }
        __syncthreads();

        // per-query running top-5
        {
            const float* row = ds + tid * 65;
            float* bdr = bd + tid * TOPK;
            int*   bir = bi + tid * TOPK;
            for (int n = 0; n < BN; n++) {
                float dv = row[n];
                if (dv < bdr[TOPK - 1]) {
                    int p = TOPK - 1;
                    while (p > 0 && bdr[p - 1] > dv) {
                        bdr[p] = bdr[p - 1]; bir[p] = bir[p - 1]; --p;
                    }
                    bdr[p] = dv; bir[p] = n0 + n;
                }
            }
        }
        __syncthreads();
    }

#pragma unroll
    for (int j = 0; j < TOPK; j++) {
        long o = ((long)tid * NSPLIT + blockIdx.x) * TOPK + j;
        g_pd[o] = bd[tid * TOPK + j];
        g_pi[o] = bi[tid * TOPK + j];
    }
}

// ---------------------------------------------------------------------------
// Merge: 128 threads per query; per-warp sorted-head merge, then cross-warp.
// ---------------------------------------------------------------------------
__global__ void knn_merge(float* __restrict__ out, int out_elems) {
    const int qy   = blockIdx.x;
    const int tid  = threadIdx.x;
    const int lane = tid & 31;
    const int w    = tid >> 5;
    const int CAND = NSPLIT * TOPK;
    const float* pd = g_pd + (long)qy * CAND;
    const int*   pi = g_pi + (long)qy * CAND;

    float d[TOPK]; int ix[TOPK];
#pragma unroll
    for (int j = 0; j < TOPK; j++) { d[j] = 3.0e38f; ix[j] = 0x7FFFFFFF; }

    for (int c = tid; c < CAND; c += 128) {
        float dv = pd[c];
        if (dv < d[TOPK - 1]) {
            int p = TOPK - 1;
            while (p > 0 && d[p - 1] > dv) { d[p] = d[p - 1]; ix[p] = ix[p - 1]; --p; }
            d[p] = dv; ix[p] = pi[c];
        }
    }

    // warp merge: 5 rounds of argmin over each lane's sorted head
    __shared__ float sd[4 * TOPK];
    __shared__ int   si[4 * TOPK];
    {
        int p = 0;
#pragma unroll
        for (int r = 0; r < TOPK; r++) {
            float v = (p < TOPK) ? d[p] : 3.0e38f;
            int  id = (p < TOPK) ? ix[p] : 0x7FFFFFFF;
#pragma unroll
            for (int o = 16; o > 0; o >>= 1) {
                float ov = __shfl_xor_sync(0xFFFFFFFFu, v, o);
                int   oi = __shfl_xor_sync(0xFFFFFFFFu, id, o);
                if (ov < v || (ov == v && oi < id)) { v = ov; id = oi; }
            }
            if (p < TOPK && d[p] == v && ix[p] == id) p++;
            if (lane == 0) { sd[w * TOPK + r] = v; si[w * TOPK + r] = id; }
        }
    }
    __syncthreads();

    // warp 0 merges the 4*5 = 20 candidates
    if (w == 0) {
        float v = (lane < 4 * TOPK) ? sd[lane] : 3.0e38f;
        int  id = (lane < 4 * TOPK) ? si[lane] : 0x7FFFFFFF;
        bool used = false;
#pragma unroll
        for (int r = 0; r < TOPK; r++) {
            float cv = used ? 3.0e38f : v;
            int   ci = used ? 0x7FFFFFFF : id;
            float bv2 = cv; int bi2 = ci;
#pragma unroll
            for (int o = 16; o > 0; o >>= 1) {
                float ov = __shfl_xor_sync(0xFFFFFFFFu, bv2, o);
                int   oi = __shfl_xor_sync(0xFFFFFFFFu, bi2, o);
                if (ov < bv2 || (ov == bv2 && oi < bi2)) { bv2 = ov; bi2 = oi; }
            }
            if (!used && bv2 == v && bi2 == id) used = true;
            if (lane == 0) {
                out[qy * TOPK + r] = bv2;
                if (out_elems >= 2 * B_Q * TOPK)
                    out[B_Q * TOPK + qy * TOPK + r] = (float)bi2;
            }
        }
    }
}

// ---------------------------------------------------------------------------
extern "C" void kernel_launch(void* const* d_in, const int* in_sizes, int n_in,
                              void* d_out, int out_size) {
    const float* qm  = (const float*)d_in[0];   // query  [256, 512] f32
    const float* mem = (const float*)d_in[1];   // memory [500000, 512] f32
    (void)in_sizes; (void)n_in;

    cudaFuncSetAttribute(knn_main, cudaFuncAttributeMaxDynamicSharedMemorySize, SMEM_BYTES);

    qsq_kernel<<<B_Q / 8, 256>>>(qm);
    knn_main<<<NSPLIT, 256, SMEM_BYTES>>>(qm, mem);
    knn_merge<<<B_Q, 128>>>((float*)d_out, out_size);
}

// round 5
// speedup vs baseline: 2.2555x; 2.2555x over previous
#include <cuda_runtime.h>
#include <cuda_bf16.h>
#include <cstdint>

// ---------------------------------------------------------------- constants
#define B_Q   256
#define DIM   512
#define N_MEM 500000
#define TOPK  5
#define BN    128
#define BK    64
#define NCH   8                       // 512 / 64
#define NTILE 3907                    // ceil(500000/128)

#define STAGE_BYTES 98304             // Ahi 32K | Alo 32K | Bhi 16K | Blo 16K
#define SMEM_BYTES  196608            // 2 stages; epilogue reuses as dist tile

// ---------------------------------------------------------------- scratch
__device__ __align__(16) __nv_bfloat16 g_qhi[B_Q * DIM];
__device__ __align__(16) __nv_bfloat16 g_qlo[B_Q * DIM];
__device__ __align__(16) __nv_bfloat16 g_mhi[(size_t)N_MEM * DIM];
__device__ __align__(16) __nv_bfloat16 g_mlo[(size_t)N_MEM * DIM];
__device__ float g_qsq[B_Q];
__device__ float g_msq[N_MEM];
__device__ float g_pd[(size_t)B_Q * NTILE * TOPK];
__device__ int   g_pi[(size_t)B_Q * NTILE * TOPK];

// ---------------------------------------------------------------- helpers
__device__ __forceinline__ uint32_t smem_u32(const void* p) {
    uint32_t a;
    asm("{ .reg .u64 t; cvta.to.shared.u64 t, %1; cvt.u32.u64 %0, t; }" : "=r"(a) : "l"(p));
    return a;
}
__device__ __forceinline__ void cp16(uint32_t dst, const void* src) {
    asm volatile("cp.async.cg.shared.global [%0], [%1], 16;" :: "r"(dst), "l"(src));
}
#define CP_COMMIT() asm volatile("cp.async.commit_group;" ::: "memory")
#define CP_WAIT0()  asm volatile("cp.async.wait_group 0;" ::: "memory")
#define CP_WAIT1()  asm volatile("cp.async.wait_group 1;" ::: "memory")

__device__ __forceinline__ void ldsm4(uint32_t a, uint32_t& r0, uint32_t& r1,
                                      uint32_t& r2, uint32_t& r3) {
    asm volatile("ldmatrix.sync.aligned.m8n8.x4.shared.b16 {%0,%1,%2,%3}, [%4];"
                 : "=r"(r0), "=r"(r1), "=r"(r2), "=r"(r3) : "r"(a));
}
__device__ __forceinline__ void mma_bf16(float* d, const uint32_t* a, const uint32_t* b) {
    asm volatile(
        "mma.sync.aligned.m16n8k16.row.col.f32.bf16.bf16.f32 "
        "{%0,%1,%2,%3}, {%4,%5,%6,%7}, {%8,%9}, {%0,%1,%2,%3};"
        : "+f"(d[0]), "+f"(d[1]), "+f"(d[2]), "+f"(d[3])
        : "r"(a[0]), "r"(a[1]), "r"(a[2]), "r"(a[3]), "r"(b[0]), "r"(b[1]));
}

// split fp32 -> bf16 hi + bf16 residual, packed as uint2 (4 values)
__device__ __forceinline__ void split4(float4 v, uint2& hu, uint2& lu) {
    __nv_bfloat162 h0 = __floats2bfloat162_rn(v.x, v.y);
    __nv_bfloat162 h1 = __floats2bfloat162_rn(v.z, v.w);
    float lx = v.x - __bfloat162float(h0.x);
    float ly = v.y - __bfloat162float(h0.y);
    float lz = v.z - __bfloat162float(h1.x);
    float lw = v.w - __bfloat162float(h1.y);
    __nv_bfloat162 l0 = __floats2bfloat162_rn(lx, ly);
    __nv_bfloat162 l1 = __floats2bfloat162_rn(lz, lw);
    hu.x = ((uint32_t)__bfloat16_as_ushort(h0.y) << 16) | __bfloat16_as_ushort(h0.x);
    hu.y = ((uint32_t)__bfloat16_as_ushort(h1.y) << 16) | __bfloat16_as_ushort(h1.x);
    lu.x = ((uint32_t)__bfloat16_as_ushort(l0.y) << 16) | __bfloat16_as_ushort(l0.x);
    lu.y = ((uint32_t)__bfloat16_as_ushort(l1.y) << 16) | __bfloat16_as_ushort(l1.x);
}

// ---------------------------------------------------------------- prep kernels
// warp per row: fp32 -> bf16 hi/lo + row sum-of-squares
__global__ void mconv_kernel(const float* __restrict__ mem) {
    int w    = (blockIdx.x * blockDim.x + threadIdx.x) >> 5;
    int lane = threadIdx.x & 31;
    if (w >= N_MEM) return;
    const float4* row = (const float4*)(mem + (size_t)w * DIM);
    uint2* dh = (uint2*)g_mhi + (size_t)w * 128;
    uint2* dl = (uint2*)g_mlo + (size_t)w * 128;
    float s = 0.f;
#pragma unroll
    for (int j = 0; j < 4; j++) {
        int f = lane + 32 * j;
        float4 v = row[f];
        uint2 hu, lu;
        split4(v, hu, lu);
        dh[f] = hu; dl[f] = lu;
        s += v.x * v.x + v.y * v.y + v.z * v.z + v.w * v.w;
    }
#pragma unroll
    for (int o = 16; o > 0; o >>= 1) s += __shfl_xor_sync(0xFFFFFFFFu, s, o);
    if (lane == 0) g_msq[w] = s;
}

__global__ void qconv_kernel(const float* __restrict__ qm) {
    int w    = (blockIdx.x * blockDim.x + threadIdx.x) >> 5;
    int lane = threadIdx.x & 31;
    if (w >= B_Q) return;
    const float4* row = (const float4*)(qm + (size_t)w * DIM);
    uint2* dh = (uint2*)g_qhi + (size_t)w * 128;
    uint2* dl = (uint2*)g_qlo + (size_t)w * 128;
    float s = 0.f;
#pragma unroll
    for (int j = 0; j < 4; j++) {
        int f = lane + 32 * j;
        float4 v = row[f];
        uint2 hu, lu;
        split4(v, hu, lu);
        dh[f] = hu; dl[f] = lu;
        s += v.x * v.x + v.y * v.y + v.z * v.z + v.w * v.w;
    }
#pragma unroll
    for (int o = 16; o > 0; o >>= 1) s += __shfl_xor_sync(0xFFFFFFFFu, s, o);
    if (lane == 0) g_qsq[w] = s;
}

// ---------------------------------------------------------------- main kernel
__global__ void __launch_bounds__(256, 1) knn_hmma() {
    extern __shared__ char smem[];
    const uint32_t sb = smem_u32(smem);
    const int tid  = threadIdx.x;
    const int lane = tid & 31;
    const int wid  = tid >> 5;
    const int wm   = wid >> 1;          // 0..3 : warp m-tile (64 queries)
    const int wn   = wid & 1;           // 0..1 : warp n-tile (64 rows)
    const int n0   = blockIdx.x * BN;

    // cp.async staging indices
    const uint4* qh4 = (const uint4*)g_qhi;
    const uint4* ql4 = (const uint4*)g_qlo;
    const uint4* mh4 = (const uint4*)g_mhi;
    const uint4* ml4 = (const uint4*)g_mlo;

    // ldmatrix per-lane address components
    const int    rowA  = wm * 64 + (lane & 15);
    const uint32_t colA = (uint32_t)((lane >> 4) << 4);
    const uint32_t xorA = (uint32_t)((rowA & 7) << 4);
    const uint32_t offA = (uint32_t)(rowA * 128);
    const int    rowB  = wn * 64 + (lane & 7) + ((lane >> 4) << 3);
    const uint32_t colB = (uint32_t)(((lane >> 3) & 1) << 4);
    const uint32_t xorB = (uint32_t)((lane & 7) << 4);
    const uint32_t offB = (uint32_t)(rowB * 128);

    float acc[4][8][4];
#pragma unroll
    for (int i = 0; i < 4; i++)
#pragma unroll
        for (int j = 0; j < 8; j++)
#pragma unroll
            for (int r = 0; r < 4; r++) acc[i][j][r] = 0.f;

    // ---- stage issue helper (inlined twice) ----
    auto stage = [&](int s, int c) {
        uint32_t base = sb + s * STAGE_BYTES;
        // A hi/lo: 2048 16B chunks each, 8 per thread
#pragma unroll
        for (int i = 0; i < 8; i++) {
            int id = i * 256 + tid;
            int r = id >> 3, c16 = id & 7;
            uint32_t doff = (uint32_t)(r * 128 + ((c16 * 16) ^ ((r & 7) << 4)));
            size_t soff = (size_t)r * 64 + c * 8 + c16;
            cp16(base + doff, qh4 + soff);
            cp16(base + 32768 + doff, ql4 + soff);
        }
        // B hi/lo: 1024 chunks each, 4 per thread
#pragma unroll
        for (int i = 0; i < 4; i++) {
            int id = i * 256 + tid;
            int r = id >> 3, c16 = id & 7;
            int grow = n0 + r;
            if (grow >= N_MEM) grow = N_MEM - 1;
            uint32_t doff = (uint32_t)(r * 128 + ((c16 * 16) ^ ((r & 7) << 4)));
            size_t soff = (size_t)grow * 64 + c * 8 + c16;
            cp16(base + 65536 + doff, mh4 + soff);
            cp16(base + 81920 + doff, ml4 + soff);
        }
        CP_COMMIT();
    };

    stage(0, 0);

    for (int c = 0; c < NCH; c++) {
        if (c + 1 < NCH) { stage((c + 1) & 1, c + 1); CP_WAIT1(); }
        else             { CP_WAIT0(); }
        __syncthreads();

        uint32_t aBase = sb + (c & 1) * STAGE_BYTES;
#pragma unroll
        for (int ks = 0; ks < 4; ks++) {
            const uint32_t kb = ks * 32;
            uint32_t Ah[4][4], Al[4][4], Bh[8][2], Bl[8][2];
            uint32_t ca = (kb + colA) ^ xorA;
            uint32_t cb = (kb + colB) ^ xorB;
#pragma unroll
            for (int mi = 0; mi < 4; mi++) {
                uint32_t ad = aBase + offA + mi * 2048 + ca;
                ldsm4(ad,          Ah[mi][0], Ah[mi][1], Ah[mi][2], Ah[mi][3]);
                ldsm4(ad + 32768,  Al[mi][0], Al[mi][1], Al[mi][2], Al[mi][3]);
            }
#pragma unroll
            for (int jp = 0; jp < 4; jp++) {
                uint32_t bd = aBase + 65536 + offB + jp * 2048 + cb;
                ldsm4(bd, Bh[jp*2][0], Bh[jp*2][1], Bh[jp*2+1][0], Bh[jp*2+1][1]);
                ldsm4(bd + 16384, Bl[jp*2][0], Bl[jp*2][1], Bl[jp*2+1][0], Bl[jp*2+1][1]);
            }
#pragma unroll
            for (int mi = 0; mi < 4; mi++)
#pragma unroll
                for (int ni = 0; ni < 8; ni++) {
                    mma_bf16(acc[mi][ni], Ah[mi], Bh[ni]);   // qh . mh
                    mma_bf16(acc[mi][ni], Ah[mi], Bl[ni]);   // qh . ml
                    mma_bf16(acc[mi][ni], Al[mi], Bh[ni]);   // ql . mh
                }
        }
        __syncthreads();
    }

    // ---- epilogue: dump dot products to smem dist tile (pitch 129) ----
    float* ds = (float*)smem;
    float* ms = (float*)(smem + 256 * 129 * 4);   // 128 floats
#pragma unroll
    for (int mi = 0; mi < 4; mi++) {
        int m = wm * 64 + mi * 16 + (lane >> 2);
#pragma unroll
        for (int ni = 0; ni < 8; ni++) {
            int n = wn * 64 + ni * 8 + (lane & 3) * 2;
            ds[m * 129 + n]           = acc[mi][ni][0];
            ds[m * 129 + n + 1]       = acc[mi][ni][1];
            ds[(m + 8) * 129 + n]     = acc[mi][ni][2];
            ds[(m + 8) * 129 + n + 1] = acc[mi][ni][3];
        }
    }
    if (tid < BN) {
        int grow = n0 + tid;
        ms[tid] = (grow < N_MEM) ? g_msq[grow] : 3.0e38f;
    }
    __syncthreads();

    // ---- per-query top-5 over this CTA's 128 columns ----
    {
        const float qsq = g_qsq[tid];
        const float* row = ds + tid * 129;
        float bd[TOPK]; int bix[TOPK];
#pragma unroll
        for (int j = 0; j < TOPK; j++) { bd[j] = 3.0e38f; bix[j] = 0x7FFFFFFF; }
        for (int n = 0; n < BN; n++) {
            float dist = qsq + ms[n] - 2.0f * row[n];
            if (dist < bd[TOPK - 1]) {
                int p = TOPK - 1;
                while (p > 0 && bd[p - 1] > dist) {
                    bd[p] = bd[p - 1]; bix[p] = bix[p - 1]; --p;
                }
                bd[p] = dist; bix[p] = n0 + n;
            }
        }
#pragma unroll
        for (int j = 0; j < TOPK; j++) {
            size_t o = ((size_t)tid * NTILE + blockIdx.x) * TOPK + j;
            g_pd[o] = bd[j];
            g_pi[o] = bix[j];
        }
    }
}

// ---------------------------------------------------------------- merge
__global__ void knn_merge(float* __restrict__ out, int out_elems) {
    const int qy   = blockIdx.x;
    const int tid  = threadIdx.x;
    const int lane = tid & 31;
    const int w    = tid >> 5;
    const int CAND = NTILE * TOPK;
    const float* pd = g_pd + (size_t)qy * CAND;
    const int*   pi = g_pi + (size_t)qy * CAND;

    float d[TOPK]; int ix[TOPK];
#pragma unroll
    for (int j = 0; j < TOPK; j++) { d[j] = 3.0e38f; ix[j] = 0x7FFFFFFF; }

    for (int c = tid; c < CAND; c += 256) {
        float dv = pd[c];
        if (dv < d[TOPK - 1]) {
            int p = TOPK - 1;
            while (p > 0 && d[p - 1] > dv) { d[p] = d[p - 1]; ix[p] = ix[p - 1]; --p; }
            d[p] = dv; ix[p] = pi[c];
        }
    }

    // per-warp sorted-head merge -> 5 per warp
    __shared__ float sd[8 * TOPK];
    __shared__ int   si[8 * TOPK];
    {
        int p = 0;
#pragma unroll
        for (int r = 0; r < TOPK; r++) {
            float v = (p < TOPK) ? d[p] : 3.0e38f;
            int  id = (p < TOPK) ? ix[p] : 0x7FFFFFFF;
#pragma unroll
            for (int o = 16; o > 0; o >>= 1) {
                float ov = __shfl_xor_sync(0xFFFFFFFFu, v, o);
                int   oi = __shfl_xor_sync(0xFFFFFFFFu, id, o);
                if (ov < v || (ov == v && oi < id)) { v = ov; id = oi; }
            }
            if (p < TOPK && d[p] == v && ix[p] == id) p++;
            if (lane == 0) { sd[w * TOPK + r] = v; si[w * TOPK + r] = id; }
        }
    }
    __syncthreads();

    // final: thread 0 merges 40 sorted-ish candidates
    if (tid == 0) {
        float fd[TOPK]; int fi[TOPK];
#pragma unroll
        for (int j = 0; j < TOPK; j++) { fd[j] = 3.0e38f; fi[j] = 0x7FFFFFFF; }
        for (int c = 0; c < 8 * TOPK; c++) {
            float dv = sd[c]; int di = si[c];
            if (dv < fd[TOPK - 1] || (dv == fd[TOPK - 1] && di < fi[TOPK - 1])) {
                int p = TOPK - 1;
                while (p > 0 && (fd[p - 1] > dv || (fd[p - 1] == dv && fi[p - 1] > di))) {
                    fd[p] = fd[p - 1]; fi[p] = fi[p - 1]; --p;
                }
                fd[p] = dv; fi[p] = di;
            }
        }
#pragma unroll
        for (int j = 0; j < TOPK; j++) {
            out[qy * TOPK + j] = fd[j];
            if (out_elems >= 2 * B_Q * TOPK)
                out[B_Q * TOPK + qy * TOPK + j] = (float)fi[j];
        }
    }
}

// ---------------------------------------------------------------- launch
extern "C" void kernel_launch(void* const* d_in, const int* in_sizes, int n_in,
                              void* d_out, int out_size) {
    const float* qm  = (const float*)d_in[0];   // query  [256, 512] f32
    const float* mem = (const float*)d_in[1];   // memory [500000, 512] f32
    (void)in_sizes; (void)n_in;

    cudaFuncSetAttribute(knn_hmma, cudaFuncAttributeMaxDynamicSharedMemorySize, SMEM_BYTES);

    mconv_kernel<<<(N_MEM + 7) / 8, 256>>>(mem);      // 62500 blocks
    qconv_kernel<<<B_Q / 8, 256>>>(qm);               // 32 blocks
    knn_hmma<<<NTILE, 256, SMEM_BYTES>>>();           // 3907 blocks
    knn_merge<<<B_Q, 256>>>((float*)d_out, out_size);
}

// round 6
// speedup vs baseline: 2.4018x; 1.0648x over previous
#include <cuda_runtime.h>
#include <cuda_bf16.h>
#include <cstdint>

// ---------------------------------------------------------------- constants
#define B_Q   256
#define DIM   512
#define N_MEM 500000
#define TOPK  5
#define BN    128
#define BK    64
#define NCH   8                       // 512 / 64
#define NTILE 3907                    // ceil(500000/128)

// smem byte offsets (single extern allocation)
//  A stage s (s=0,1): Ahi @ s*65536, Alo @ s*65536+32768     (128 KB)
//  B bf16 hi @ 131072 (16 KB), lo @ 147456 (16 KB)
//  B fp32 staging @ 163840 (32 KB)
//  msq @ 196608 (512 B)
//  epilogue dist tile reuses [0 .. 132096)
#define SM_BH  131072
#define SM_BL  147456
#define SM_BF  163840
#define SM_MS  196608
#define SMEM_BYTES 197120

// ---------------------------------------------------------------- scratch
__device__ __align__(16) __nv_bfloat16 g_qhi[B_Q * DIM];
__device__ __align__(16) __nv_bfloat16 g_qlo[B_Q * DIM];
__device__ float g_qsq[B_Q];
__device__ float g_pd[(size_t)B_Q * NTILE * TOPK];
__device__ int   g_pi[(size_t)B_Q * NTILE * TOPK];

// ---------------------------------------------------------------- helpers
__device__ __forceinline__ uint32_t smem_u32(const void* p) {
    uint32_t a;
    asm("{ .reg .u64 t; cvta.to.shared.u64 t, %1; cvt.u32.u64 %0, t; }" : "=r"(a) : "l"(p));
    return a;
}
__device__ __forceinline__ void cp16(uint32_t dst, const void* src) {
    asm volatile("cp.async.cg.shared.global [%0], [%1], 16;" :: "r"(dst), "l"(src));
}
#define CP_COMMIT() asm volatile("cp.async.commit_group;" ::: "memory")
#define CP_WAIT0()  asm volatile("cp.async.wait_group 0;" ::: "memory")

__device__ __forceinline__ void ldsm4(uint32_t a, uint32_t& r0, uint32_t& r1,
                                      uint32_t& r2, uint32_t& r3) {
    asm volatile("ldmatrix.sync.aligned.m8n8.x4.shared.b16 {%0,%1,%2,%3}, [%4];"
                 : "=r"(r0), "=r"(r1), "=r"(r2), "=r"(r3) : "r"(a));
}
__device__ __forceinline__ void mma_bf16(float* d, const uint32_t* a, const uint32_t* b) {
    asm volatile(
        "mma.sync.aligned.m16n8k16.row.col.f32.bf16.bf16.f32 "
        "{%0,%1,%2,%3}, {%4,%5,%6,%7}, {%8,%9}, {%0,%1,%2,%3};"
        : "+f"(d[0]), "+f"(d[1]), "+f"(d[2]), "+f"(d[3])
        : "r"(a[0]), "r"(a[1]), "r"(a[2]), "r"(a[3]), "r"(b[0]), "r"(b[1]));
}

// split fp32 -> bf16 hi + bf16 residual, packed as uint2 (4 values)
__device__ __forceinline__ void split4(float4 v, uint2& hu, uint2& lu) {
    __nv_bfloat162 h0 = __floats2bfloat162_rn(v.x, v.y);
    __nv_bfloat162 h1 = __floats2bfloat162_rn(v.z, v.w);
    float lx = v.x - __bfloat162float(h0.x);
    float ly = v.y - __bfloat162float(h0.y);
    float lz = v.z - __bfloat162float(h1.x);
    float lw = v.w - __bfloat162float(h1.y);
    __nv_bfloat162 l0 = __floats2bfloat162_rn(lx, ly);
    __nv_bfloat162 l1 = __floats2bfloat162_rn(lz, lw);
    hu.x = ((uint32_t)__bfloat16_as_ushort(h0.y) << 16) | __bfloat16_as_ushort(h0.x);
    hu.y = ((uint32_t)__bfloat16_as_ushort(h1.y) << 16) | __bfloat16_as_ushort(h1.x);
    lu.x = ((uint32_t)__bfloat16_as_ushort(l0.y) << 16) | __bfloat16_as_ushort(l0.x);
    lu.y = ((uint32_t)__bfloat16_as_ushort(l1.y) << 16) | __bfloat16_as_ushort(l1.x);
}

// ---------------------------------------------------------------- prep kernel
// queries only: fp32 -> bf16 hi/lo + ||q||^2 (tiny: 256 rows)
__global__ void qconv_kernel(const float* __restrict__ qm) {
    int w    = (blockIdx.x * blockDim.x + threadIdx.x) >> 5;
    int lane = threadIdx.x & 31;
    if (w >= B_Q) return;
    const float4* row = (const float4*)(qm + (size_t)w * DIM);
    uint2* dh = (uint2*)g_qhi + (size_t)w * 128;
    uint2* dl = (uint2*)g_qlo + (size_t)w * 128;
    float s = 0.f;
#pragma unroll
    for (int j = 0; j < 4; j++) {
        int f = lane + 32 * j;
        float4 v = row[f];
        uint2 hu, lu;
        split4(v, hu, lu);
        dh[f] = hu; dl[f] = lu;
        s += v.x * v.x + v.y * v.y + v.z * v.z + v.w * v.w;
    }
#pragma unroll
    for (int o = 16; o > 0; o >>= 1) s += __shfl_xor_sync(0xFFFFFFFFu, s, o);
    if (lane == 0) g_qsq[w] = s;
}

// ---------------------------------------------------------------- main kernel
__global__ void __launch_bounds__(256, 1) knn_hmma(const float* __restrict__ mem) {
    extern __shared__ char smem[];
    const uint32_t sb = smem_u32(smem);
    const int tid  = threadIdx.x;
    const int lane = tid & 31;
    const int wid  = tid >> 5;
    const int wm   = wid >> 1;          // 0..3 : warp m-tile (64 queries)
    const int wn   = wid & 1;           // 0..1 : warp n-tile (64 rows)
    const int n0   = blockIdx.x * BN;

    const uint4* qh4 = (const uint4*)g_qhi;
    const uint4* ql4 = (const uint4*)g_qlo;

    // ldmatrix per-lane address components (A: 16x16 frags, B: 16x8 pairs)
    const int      rowA = wm * 64 + (lane & 15);
    const uint32_t colA = (uint32_t)((lane >> 4) << 4);
    const uint32_t xorA = (uint32_t)((rowA & 7) << 4);
    const uint32_t offA = (uint32_t)(rowA * 128);
    const int      rowB = wn * 64 + (lane & 7) + ((lane >> 4) << 3);
    const uint32_t colB = (uint32_t)(((lane >> 3) & 1) << 4);
    const uint32_t xorB = (uint32_t)((lane & 7) << 4);
    const uint32_t offB = (uint32_t)(rowB * 128);

    float acc[4][8][4];
#pragma unroll
    for (int i = 0; i < 4; i++)
#pragma unroll
        for (int j = 0; j < 8; j++)
#pragma unroll
            for (int r = 0; r < 4; r++) acc[i][j][r] = 0.f;

    // ---- async staging of chunk c: A bf16 (precomputed) + B fp32 (raw) ----
    auto stage = [&](int c) {
        uint32_t aBase = sb + (c & 1) * 65536;
        // A hi/lo: 2048 16B chunks each, 8 per thread
#pragma unroll
        for (int i = 0; i < 8; i++) {
            int id = i * 256 + tid;
            int r = id >> 3, c16 = id & 7;
            uint32_t doff = (uint32_t)(r * 128 + ((c16 * 16) ^ ((r & 7) << 4)));
            size_t soff = (size_t)r * 64 + c * 8 + c16;
            cp16(aBase + doff, qh4 + soff);
            cp16(aBase + 32768 + doff, ql4 + soff);
        }
        // B fp32: 128 rows x 64 floats = 2048 16B chunks, 8 per thread
#pragma unroll
        for (int i = 0; i < 8; i++) {
            int id = i * 256 + tid;
            int r = id >> 4, c16 = id & 15;
            int grow = n0 + r;
            if (grow >= N_MEM) grow = N_MEM - 1;
            uint32_t doff = (uint32_t)(r * 256 + ((c16 * 16) ^ ((r & 15) << 4)));
            cp16(sb + SM_BF + doff,
                 (const char*)(mem + (size_t)grow * DIM) + ((size_t)c * 16 + c16) * 16);
        }
        CP_COMMIT();
    };

    // init msq accumulator
    if (tid < BN) ((float*)(smem + SM_MS))[tid] = 0.f;

    stage(0);

    for (int c = 0; c < NCH; c++) {
        CP_WAIT0();
        __syncthreads();

        // ---- convert B fp32 -> bf16 hi/lo in smem, fused ||m||^2 ----
        {
            float* msp = (float*)(smem + SM_MS);
#pragma unroll
            for (int i = 0; i < 8; i++) {
                int id = i * 256 + tid;
                int r = id >> 4, c16 = id & 15;
                uint32_t foff = (uint32_t)(r * 256 + ((c16 * 16) ^ ((r & 15) << 4)));
                float4 v = *(const float4*)(smem + SM_BF + foff);
                uint2 hu, lu;
                split4(v, hu, lu);
                uint32_t boff = (uint32_t)(r * 128 + ((c16 * 8) ^ ((r & 7) << 4)));
                *(uint2*)(smem + SM_BH + boff) = hu;
                *(uint2*)(smem + SM_BL + boff) = lu;
                float s = v.x * v.x + v.y * v.y + v.z * v.z + v.w * v.w;
                s += __shfl_xor_sync(0xFFFFFFFFu, s, 1);
                s += __shfl_xor_sync(0xFFFFFFFFu, s, 2);
                s += __shfl_xor_sync(0xFFFFFFFFu, s, 4);
                s += __shfl_xor_sync(0xFFFFFFFFu, s, 8);
                if ((tid & 15) == 0) msp[r] += s;
            }
        }
        __syncthreads();

        // prefetch next chunk under the MMA section
        if (c + 1 < NCH) stage(c + 1);

        uint32_t aBase = sb + (c & 1) * 65536;
#pragma unroll
        for (int ks = 0; ks < 4; ks++) {
            const uint32_t kb = ks * 32;
            uint32_t Ah[4][4], Al[4][4], Bh[8][2], Bl[8][2];
            uint32_t ca = (kb + colA) ^ xorA;
            uint32_t cb = (kb + colB) ^ xorB;
#pragma unroll
            for (int mi = 0; mi < 4; mi++) {
                uint32_t ad = aBase + offA + mi * 2048 + ca;
                ldsm4(ad,         Ah[mi][0], Ah[mi][1], Ah[mi][2], Ah[mi][3]);
                ldsm4(ad + 32768, Al[mi][0], Al[mi][1], Al[mi][2], Al[mi][3]);
            }
#pragma unroll
            for (int jp = 0; jp < 4; jp++) {
                uint32_t bd = sb + SM_BH + offB + jp * 2048 + cb;
                ldsm4(bd,         Bh[jp*2][0], Bh[jp*2][1], Bh[jp*2+1][0], Bh[jp*2+1][1]);
                ldsm4(bd + 16384, Bl[jp*2][0], Bl[jp*2][1], Bl[jp*2+1][0], Bl[jp*2+1][1]);
            }
            // term-major: 32 independent MMAs between reuses of any accumulator
#pragma unroll
            for (int mi = 0; mi < 4; mi++)
#pragma unroll
                for (int ni = 0; ni < 8; ni++)
                    mma_bf16(acc[mi][ni], Ah[mi], Bh[ni]);   // qh . mh
#pragma unroll
            for (int mi = 0; mi < 4; mi++)
#pragma unroll
                for (int ni = 0; ni < 8; ni++)
                    mma_bf16(acc[mi][ni], Ah[mi], Bl[ni]);   // qh . ml
#pragma unroll
            for (int mi = 0; mi < 4; mi++)
#pragma unroll
                for (int ni = 0; ni < 8; ni++)
                    mma_bf16(acc[mi][ni], Al[mi], Bh[ni]);   // ql . mh
        }
        __syncthreads();
    }

    // ---- epilogue: dump dot products to smem dist tile (pitch 129) ----
    float* ds = (float*)smem;
    const float* msp = (const float*)(smem + SM_MS);
#pragma unroll
    for (int mi = 0; mi < 4; mi++) {
        int m = wm * 64 + mi * 16 + (lane >> 2);
#pragma unroll
        for (int ni = 0; ni < 8; ni++) {
            int n = wn * 64 + ni * 8 + (lane & 3) * 2;
            ds[m * 129 + n]           = acc[mi][ni][0];
            ds[m * 129 + n + 1]       = acc[mi][ni][1];
            ds[(m + 8) * 129 + n]     = acc[mi][ni][2];
            ds[(m + 8) * 129 + n + 1] = acc[mi][ni][3];
        }
    }
    __syncthreads();

    // ---- per-query top-5 over this CTA's 128 columns ----
    {
        const float qsq = g_qsq[tid];
        const float* row = ds + tid * 129;
        const int nvalid = (n0 + BN <= N_MEM) ? BN : (N_MEM - n0);
        float bd[TOPK]; int bix[TOPK];
#pragma unroll
        for (int j = 0; j < TOPK; j++) { bd[j] = 3.0e38f; bix[j] = 0x7FFFFFFF; }
        for (int n = 0; n < nvalid; n++) {
            float dist = qsq + msp[n] - 2.0f * row[n];
            if (dist < bd[TOPK - 1]) {
                int p = TOPK - 1;
                while (p > 0 && bd[p - 1] > dist) {
                    bd[p] = bd[p - 1]; bix[p] = bix[p - 1]; --p;
                }
                bd[p] = dist; bix[p] = n0 + n;
            }
        }
#pragma unroll
        for (int j = 0; j < TOPK; j++) {
            size_t o = ((size_t)tid * NTILE + blockIdx.x) * TOPK + j;
            g_pd[o] = bd[j];
            g_pi[o] = bix[j];
        }
    }
}

// ---------------------------------------------------------------- merge
__global__ void knn_merge(float* __restrict__ out, int out_elems) {
    const int qy   = blockIdx.x;
    const int tid  = threadIdx.x;
    const int lane = tid & 31;
    const int w    = tid >> 5;
    const int CAND = NTILE * TOPK;
    const float* pd = g_pd + (size_t)qy * CAND;
    const int*   pi = g_pi + (size_t)qy * CAND;

    float d[TOPK]; int ix[TOPK];
#pragma unroll
    for (int j = 0; j < TOPK; j++) { d[j] = 3.0e38f; ix[j] = 0x7FFFFFFF; }

    for (int c = tid; c < CAND; c += 256) {
        float dv = pd[c];
        if (dv < d[TOPK - 1]) {
            int p = TOPK - 1;
            while (p > 0 && d[p - 1] > dv) { d[p] = d[p - 1]; ix[p] = ix[p - 1]; --p; }
            d[p] = dv; ix[p] = pi[c];
        }
    }

    __shared__ float sd[8 * TOPK];
    __shared__ int   si[8 * TOPK];
    {
        int p = 0;
#pragma unroll
        for (int r = 0; r < TOPK; r++) {
            float v = (p < TOPK) ? d[p] : 3.0e38f;
            int  id = (p < TOPK) ? ix[p] : 0x7FFFFFFF;
#pragma unroll
            for (int o = 16; o > 0; o >>= 1) {
                float ov = __shfl_xor_sync(0xFFFFFFFFu, v, o);
                int   oi = __shfl_xor_sync(0xFFFFFFFFu, id, o);
                if (ov < v || (ov == v && oi < id)) { v = ov; id = oi; }
            }
            if (p < TOPK && d[p] == v && ix[p] == id) p++;
            if (lane == 0) { sd[w * TOPK + r] = v; si[w * TOPK + r] = id; }
        }
    }
    __syncthreads();

    if (tid == 0) {
        float fd[TOPK]; int fi[TOPK];
#pragma unroll
        for (int j = 0; j < TOPK; j++) { fd[j] = 3.0e38f; fi[j] = 0x7FFFFFFF; }
        for (int c = 0; c < 8 * TOPK; c++) {
            float dv = sd[c]; int di = si[c];
            if (dv < fd[TOPK - 1] || (dv == fd[TOPK - 1] && di < fi[TOPK - 1])) {
                int p = TOPK - 1;
                while (p > 0 && (fd[p - 1] > dv || (fd[p - 1] == dv && fi[p - 1] > di))) {
                    fd[p] = fd[p - 1]; fi[p] = fi[p - 1]; --p;
                }
                fd[p] = dv; fi[p] = di;
            }
        }
#pragma unroll
        for (int j = 0; j < TOPK; j++) {
            out[qy * TOPK + j] = fd[j];
            if (out_elems >= 2 * B_Q * TOPK)
                out[B_Q * TOPK + qy * TOPK + j] = (float)fi[j];
        }
    }
}

// ---------------------------------------------------------------- launch
extern "C" void kernel_launch(void* const* d_in, const int* in_sizes, int n_in,
                              void* d_out, int out_size) {
    const float* qm  = (const float*)d_in[0];   // query  [256, 512] f32
    const float* mem = (const float*)d_in[1];   // memory [500000, 512] f32
    (void)in_sizes; (void)n_in;

    cudaFuncSetAttribute(knn_hmma, cudaFuncAttributeMaxDynamicSharedMemorySize, SMEM_BYTES);

    qconv_kernel<<<B_Q / 8, 256>>>(qm);           // 32 blocks (queries only)
    knn_hmma<<<NTILE, 256, SMEM_BYTES>>>(mem);    // 3907 blocks, fused convert
    knn_merge<<<B_Q, 256>>>((float*)d_out, out_size);
}

// round 7
// speedup vs baseline: 2.4573x; 1.0231x over previous
#include <cuda_runtime.h>
#include <cuda_bf16.h>
#include <cstdint>

// ---------------------------------------------------------------- constants
#define B_Q   256
#define DIM   512
#define N_MEM 500000
#define TOPK  5
#define BN    128
#define KC    32
#define NCH   16                      // 512 / 32
#define NTILE 3907                    // ceil(500000/128)
#define PITCH 80                      // bytes per smem row (32 bf16 + 16B pad)

// smem layout (bytes)
//  A: [stage][hi/lo][256 rows x PITCH]  2*2*20480 = 81920
//  B: [stage][hi/lo][128 rows x PITCH]  2*2*10240 = 40960   @ 81920
//  msq accum: 512B                                          @ 132096
//  epilogue dist tile 256*129*4 = 132096 reuses [0,132096)
#define A_ST   40960
#define A_HL   20480
#define SM_B   81920
#define B_ST   20480
#define B_HL   10240
#define SM_MS  132096
#define SMEM_BYTES 132608

// ---------------------------------------------------------------- scratch
__device__ __align__(16) __nv_bfloat16 g_qhi[B_Q * DIM];
__device__ __align__(16) __nv_bfloat16 g_qlo[B_Q * DIM];
__device__ float g_qsq[B_Q];
__device__ float g_pd[(size_t)B_Q * NTILE * TOPK];
__device__ int   g_pi[(size_t)B_Q * NTILE * TOPK];

// ---------------------------------------------------------------- helpers
__device__ __forceinline__ uint32_t smem_u32(const void* p) {
    uint32_t a;
    asm("{ .reg .u64 t; cvta.to.shared.u64 t, %1; cvt.u32.u64 %0, t; }" : "=r"(a) : "l"(p));
    return a;
}
__device__ __forceinline__ void cp16(uint32_t dst, const void* src) {
    asm volatile("cp.async.cg.shared.global [%0], [%1], 16;" :: "r"(dst), "l"(src));
}
#define CP_COMMIT() asm volatile("cp.async.commit_group;" ::: "memory")
#define CP_WAIT0()  asm volatile("cp.async.wait_group 0;" ::: "memory")

__device__ __forceinline__ void ldsm4(uint32_t a, uint32_t& r0, uint32_t& r1,
                                      uint32_t& r2, uint32_t& r3) {
    asm volatile("ldmatrix.sync.aligned.m8n8.x4.shared.b16 {%0,%1,%2,%3}, [%4];"
                 : "=r"(r0), "=r"(r1), "=r"(r2), "=r"(r3) : "r"(a));
}
__device__ __forceinline__ void mma_bf16(float* d, const uint32_t* a, const uint32_t* b) {
    asm volatile(
        "mma.sync.aligned.m16n8k16.row.col.f32.bf16.bf16.f32 "
        "{%0,%1,%2,%3}, {%4,%5,%6,%7}, {%8,%9}, {%0,%1,%2,%3};"
        : "+f"(d[0]), "+f"(d[1]), "+f"(d[2]), "+f"(d[3])
        : "r"(a[0]), "r"(a[1]), "r"(a[2]), "r"(a[3]), "r"(b[0]), "r"(b[1]));
}

// split fp32 -> bf16 hi + bf16 residual, packed as uint2 (4 values)
__device__ __forceinline__ void split4(float4 v, uint2& hu, uint2& lu) {
    __nv_bfloat162 h0 = __floats2bfloat162_rn(v.x, v.y);
    __nv_bfloat162 h1 = __floats2bfloat162_rn(v.z, v.w);
    float lx = v.x - __bfloat162float(h0.x);
    float ly = v.y - __bfloat162float(h0.y);
    float lz = v.z - __bfloat162float(h1.x);
    float lw = v.w - __bfloat162float(h1.y);
    __nv_bfloat162 l0 = __floats2bfloat162_rn(lx, ly);
    __nv_bfloat162 l1 = __floats2bfloat162_rn(lz, lw);
    hu.x = ((uint32_t)__bfloat16_as_ushort(h0.y) << 16) | __bfloat16_as_ushort(h0.x);
    hu.y = ((uint32_t)__bfloat16_as_ushort(h1.y) << 16) | __bfloat16_as_ushort(h1.x);
    lu.x = ((uint32_t)__bfloat16_as_ushort(l0.y) << 16) | __bfloat16_as_ushort(l0.x);
    lu.y = ((uint32_t)__bfloat16_as_ushort(l1.y) << 16) | __bfloat16_as_ushort(l1.x);
}

// ---------------------------------------------------------------- prep kernel
__global__ void qconv_kernel(const float* __restrict__ qm) {
    int w    = (blockIdx.x * blockDim.x + threadIdx.x) >> 5;
    int lane = threadIdx.x & 31;
    if (w >= B_Q) return;
    const float4* row = (const float4*)(qm + (size_t)w * DIM);
    uint2* dh = (uint2*)g_qhi + (size_t)w * 128;
    uint2* dl = (uint2*)g_qlo + (size_t)w * 128;
    float s = 0.f;
#pragma unroll
    for (int j = 0; j < 4; j++) {
        int f = lane + 32 * j;
        float4 v = row[f];
        uint2 hu, lu;
        split4(v, hu, lu);
        dh[f] = hu; dl[f] = lu;
        s += v.x * v.x + v.y * v.y + v.z * v.z + v.w * v.w;
    }
#pragma unroll
    for (int o = 16; o > 0; o >>= 1) s += __shfl_xor_sync(0xFFFFFFFFu, s, o);
    if (lane == 0) g_qsq[w] = s;
}

// ---------------------------------------------------------------- main kernel
__global__ void __launch_bounds__(256, 1) knn_hmma(const float* __restrict__ mem) {
    extern __shared__ char smem[];
    const uint32_t sb = smem_u32(smem);
    const int tid  = threadIdx.x;
    const int lane = tid & 31;
    const int wid  = tid >> 5;
    const int wm   = wid >> 1;          // 0..3 : warp m-tile (64 queries)
    const int wn   = wid & 1;           // 0..1 : warp n-tile (64 rows)
    const int n0   = blockIdx.x * BN;

    float* msp = (float*)(smem + SM_MS);
    if (tid < BN) msp[tid] = 0.f;

    // ldsm per-lane offsets (pitch-80 rows; conflict-free, no XOR needed)
    const uint32_t offA = (uint32_t)((wm * 64 + (lane & 15)) * PITCH + ((lane >> 4) << 4));
    const uint32_t offB = (uint32_t)((wn * 64 + (lane & 7) + ((lane >> 4) << 3)) * PITCH
                                     + (((lane >> 3) & 1) << 4));

    float acc[4][8][4];
#pragma unroll
    for (int i = 0; i < 4; i++)
#pragma unroll
        for (int j = 0; j < 8; j++)
#pragma unroll
            for (int r = 0; r < 4; r++) acc[i][j][r] = 0.f;

    // B register prefetch: thread owns (row = tid>>1, half = tid&1) -> 16 floats
    const int browf = tid >> 1;
    int grow = n0 + browf;
    if (grow >= N_MEM) grow = N_MEM - 1;
    const float4* bsrc = (const float4*)(mem + (size_t)grow * DIM) + (tid & 1) * 4;

    // A staging: 8 cp16/thread (4 hi + 4 lo)
    auto stageA = [&](int c) {
        uint32_t base = sb + (c & 1) * A_ST;
#pragma unroll
        for (int i = 0; i < 8; i++) {
            int idx = (i & 3) * 256 + tid;          // [0,1024)
            int r = idx >> 2, j = idx & 3;
            uint32_t d = base + ((i < 4) ? 0 : A_HL) + (uint32_t)(r * PITCH + j * 16);
            const char* s = (const char*)((i < 4) ? g_qhi : g_qlo)
                            + (size_t)r * 1024 + (size_t)c * 64 + (size_t)j * 16;
            cp16(d, s);
        }
        CP_COMMIT();
    };

    float4 pb[4];
    stageA(0);
#pragma unroll
    for (int q = 0; q < 4; q++) pb[q] = bsrc[q];
    __syncthreads();   // msp zero visible

    for (int c = 0; c < NCH; c++) {
        // ---- convert chunk c's B registers -> bf16 hi/lo smem (buffer c&1) ----
        {
            char* bh = smem + SM_B + (c & 1) * B_ST;
            char* bl = bh + B_HL;
            uint32_t off0 = (uint32_t)(browf * PITCH + (tid & 1) * 32);
            float s = 0.f;
#pragma unroll
            for (int q = 0; q < 4; q++) {
                float4 v = pb[q];
                uint2 hu, lu;
                split4(v, hu, lu);
                *(uint2*)(bh + off0 + q * 8) = hu;
                *(uint2*)(bl + off0 + q * 8) = lu;
                s += v.x * v.x + v.y * v.y + v.z * v.z + v.w * v.w;
            }
            s += __shfl_xor_sync(0xFFFFFFFFu, s, 1);
            if (!(tid & 1)) msp[browf] += s;
        }

        // ---- prefetch next chunk's B into registers (hides under MMA below) ----
        if (c + 1 < NCH) {
#pragma unroll
            for (int q = 0; q < 4; q++) pb[q] = bsrc[(c + 1) * 8 + q];
        }

        CP_WAIT0();         // A(c) arrived (A(c+1) not yet committed)
        __syncthreads();    // all warps done with MMA(c-1) + see STS/A(c)

        if (c + 1 < NCH) stageA(c + 1);   // safe: everyone is past MMA(c-1)

        // ---- MMA chunk c ----
        uint32_t aB = sb + (c & 1) * A_ST;
        uint32_t bB = sb + SM_B + (c & 1) * B_ST;
#pragma unroll
        for (int ks = 0; ks < 2; ks++) {
            const uint32_t ka = ks * 32;
            uint32_t Ah[4][4], Al[4][4], Bh[8][2], Bl[8][2];
#pragma unroll
            for (int mi = 0; mi < 4; mi++) {
                uint32_t ad = aB + mi * 16 * PITCH + offA + ka;
                ldsm4(ad,        Ah[mi][0], Ah[mi][1], Ah[mi][2], Ah[mi][3]);
                ldsm4(ad + A_HL, Al[mi][0], Al[mi][1], Al[mi][2], Al[mi][3]);
            }
#pragma unroll
            for (int jp = 0; jp < 4; jp++) {
                uint32_t bd = bB + jp * 16 * PITCH + offB + ka;
                ldsm4(bd,        Bh[jp*2][0], Bh[jp*2][1], Bh[jp*2+1][0], Bh[jp*2+1][1]);
                ldsm4(bd + B_HL, Bl[jp*2][0], Bl[jp*2][1], Bl[jp*2+1][0], Bl[jp*2+1][1]);
            }
            // term-major: 32 independent tiles between accumulator reuses
#pragma unroll
            for (int mi = 0; mi < 4; mi++)
#pragma unroll
                for (int ni = 0; ni < 8; ni++)
                    mma_bf16(acc[mi][ni], Ah[mi], Bh[ni]);   // qh . mh
#pragma unroll
            for (int mi = 0; mi < 4; mi++)
#pragma unroll
                for (int ni = 0; ni < 8; ni++)
                    mma_bf16(acc[mi][ni], Ah[mi], Bl[ni]);   // qh . ml
#pragma unroll
            for (int mi = 0; mi < 4; mi++)
#pragma unroll
                for (int ni = 0; ni < 8; ni++)
                    mma_bf16(acc[mi][ni], Al[mi], Bh[ni]);   // ql . mh
        }
    }
    __syncthreads();

    // ---- epilogue: dot products -> smem dist tile (pitch 129 floats) ----
    float* ds = (float*)smem;
#pragma unroll
    for (int mi = 0; mi < 4; mi++) {
        int m = wm * 64 + mi * 16 + (lane >> 2);
#pragma unroll
        for (int ni = 0; ni < 8; ni++) {
            int n = wn * 64 + ni * 8 + (lane & 3) * 2;
            ds[m * 129 + n]           = acc[mi][ni][0];
            ds[m * 129 + n + 1]       = acc[mi][ni][1];
            ds[(m + 8) * 129 + n]     = acc[mi][ni][2];
            ds[(m + 8) * 129 + n + 1] = acc[mi][ni][3];
        }
    }
    __syncthreads();

    // ---- per-query top-5 over this CTA's 128 columns ----
    {
        const float qsq = g_qsq[tid];
        const float* row = ds + tid * 129;
        const int nvalid = (n0 + BN <= N_MEM) ? BN : (N_MEM - n0);
        float bd[TOPK]; int bix[TOPK];
#pragma unroll
        for (int j = 0; j < TOPK; j++) { bd[j] = 3.0e38f; bix[j] = 0x7FFFFFFF; }
        for (int n = 0; n < nvalid; n++) {
            float dist = qsq + msp[n] - 2.0f * row[n];
            if (dist < bd[TOPK - 1]) {
                int p = TOPK - 1;
                while (p > 0 && bd[p - 1] > dist) {
                    bd[p] = bd[p - 1]; bix[p] = bix[p - 1]; --p;
                }
                bd[p] = dist; bix[p] = n0 + n;
            }
        }
#pragma unroll
        for (int j = 0; j < TOPK; j++) {
            size_t o = ((size_t)tid * NTILE + blockIdx.x) * TOPK + j;
            g_pd[o] = bd[j];
            g_pi[o] = bix[j];
        }
    }
}

// ---------------------------------------------------------------- merge
__global__ void knn_merge(float* __restrict__ out, int out_elems) {
    const int qy   = blockIdx.x;
    const int tid  = threadIdx.x;
    const int lane = tid & 31;
    const int w    = tid >> 5;
    const int CAND = NTILE * TOPK;
    const float* pd = g_pd + (size_t)qy * CAND;
    const int*   pi = g_pi + (size_t)qy * CAND;

    float d[TOPK]; int ix[TOPK];
#pragma unroll
    for (int j = 0; j < TOPK; j++) { d[j] = 3.0e38f; ix[j] = 0x7FFFFFFF; }

    for (int c = tid; c < CAND; c += 256) {
        float dv = pd[c];
        if (dv < d[TOPK - 1]) {
            int p = TOPK - 1;
            while (p > 0 && d[p - 1] > dv) { d[p] = d[p - 1]; ix[p] = ix[p - 1]; --p; }
            d[p] = dv; ix[p] = pi[c];
        }
    }

    __shared__ float sd[8 * TOPK];
    __shared__ int   si[8 * TOPK];
    {
        int p = 0;
#pragma unroll
        for (int r = 0; r < TOPK; r++) {
            float v = (p < TOPK) ? d[p] : 3.0e38f;
            int  id = (p < TOPK) ? ix[p] : 0x7FFFFFFF;
#pragma unroll
            for (int o = 16; o > 0; o >>= 1) {
                float ov = __shfl_xor_sync(0xFFFFFFFFu, v, o);
                int   oi = __shfl_xor_sync(0xFFFFFFFFu, id, o);
                if (ov < v || (ov == v && oi < id)) { v = ov; id = oi; }
            }
            if (p < TOPK && d[p] == v && ix[p] == id) p++;
            if (lane == 0) { sd[w * TOPK + r] = v; si[w * TOPK + r] = id; }
        }
    }
    __syncthreads();

    if (tid == 0) {
        float fd[TOPK]; int fi[TOPK];
#pragma unroll
        for (int j = 0; j < TOPK; j++) { fd[j] = 3.0e38f; fi[j] = 0x7FFFFFFF; }
        for (int c = 0; c < 8 * TOPK; c++) {
            float dv = sd[c]; int di = si[c];
            if (dv < fd[TOPK - 1] || (dv == fd[TOPK - 1] && di < fi[TOPK - 1])) {
                int p = TOPK - 1;
                while (p > 0 && (fd[p - 1] > dv || (fd[p - 1] == dv && fi[p - 1] > di))) {
                    fd[p] = fd[p - 1]; fi[p] = fi[p - 1]; --p;
                }
                fd[p] = dv; fi[p] = di;
            }
        }
#pragma unroll
        for (int j = 0; j < TOPK; j++) {
            out[qy * TOPK + j] = fd[j];
            if (out_elems >= 2 * B_Q * TOPK)
                out[B_Q * TOPK + qy * TOPK + j] = (float)fi[j];
        }
    }
}

// ---------------------------------------------------------------- launch
extern "C" void kernel_launch(void* const* d_in, const int* in_sizes, int n_in,
                              void* d_out, int out_size) {
    const float* qm  = (const float*)d_in[0];   // query  [256, 512] f32
    const float* mem = (const float*)d_in[1];   // memory [500000, 512] f32
    (void)in_sizes; (void)n_in;

    cudaFuncSetAttribute(knn_hmma, cudaFuncAttributeMaxDynamicSharedMemorySize, SMEM_BYTES);

    qconv_kernel<<<B_Q / 8, 256>>>(qm);
    knn_hmma<<<NTILE, 256, SMEM_BYTES>>>(mem);
    knn_merge<<<B_Q, 256>>>((float*)d_out, out_size);
}

// round 8
// speedup vs baseline: 3.7092x; 1.5094x over previous
#include <cuda_runtime.h>
#include <cuda_bf16.h>
#include <cstdint>

// ---------------------------------------------------------------- constants
#define B_Q    256
#define DIM    512
#define N_MEM  500000
#define TOPK   5
#define BN     128
#define KC     64
#define NCH    8                       // 512 / 64
#define NTILE  3907                    // ceil(500000/128)
#define TILE_K 4                       // approx top-k kept per tile
#define GK     20                      // global approx candidates rescored exactly

#define PITCH  144                     // bf16 tile row pitch (128B data + 16 pad)
#define FPITCH 272                     // fp32 staging row pitch (256B data + 16 pad)

// smem layout (bytes)
#define SM_A   0                       // A bf16 db: 2 * 256*144 = 73728
#define SM_BB  73728                   // B bf16 db: 2 * 128*144 = 36864
#define SM_BF  110592                  // B fp32 db: 2 * 128*272 = 69632
#define SM_MS  180224                  // 128 floats ||m||^2
#define SMEM_BYTES 180992
// epilogue dist tile (256*129*4 = 132096) reuses [0, 132096)

// ---------------------------------------------------------------- scratch
__device__ __align__(16) __nv_bfloat16 g_qhi[B_Q * DIM];
__device__ float g_qsq[B_Q];
__device__ float g_pd[(size_t)B_Q * NTILE * TILE_K];
__device__ int   g_pi[(size_t)B_Q * NTILE * TILE_K];

// ---------------------------------------------------------------- helpers
__device__ __forceinline__ uint32_t smem_u32(const void* p) {
    uint32_t a;
    asm("{ .reg .u64 t; cvta.to.shared.u64 t, %1; cvt.u32.u64 %0, t; }" : "=r"(a) : "l"(p));
    return a;
}
__device__ __forceinline__ void cp16(uint32_t dst, const void* src) {
    asm volatile("cp.async.cg.shared.global [%0], [%1], 16;" :: "r"(dst), "l"(src));
}
#define CP_COMMIT() asm volatile("cp.async.commit_group;" ::: "memory")
#define CP_WAIT0()  asm volatile("cp.async.wait_group 0;" ::: "memory")

__device__ __forceinline__ void ldsm4(uint32_t a, uint32_t& r0, uint32_t& r1,
                                      uint32_t& r2, uint32_t& r3) {
    asm volatile("ldmatrix.sync.aligned.m8n8.x4.shared.b16 {%0,%1,%2,%3}, [%4];"
                 : "=r"(r0), "=r"(r1), "=r"(r2), "=r"(r3) : "r"(a));
}
__device__ __forceinline__ void mma_bf16(float* d, const uint32_t* a, const uint32_t* b) {
    asm volatile(
        "mma.sync.aligned.m16n8k16.row.col.f32.bf16.bf16.f32 "
        "{%0,%1,%2,%3}, {%4,%5,%6,%7}, {%8,%9}, {%0,%1,%2,%3};"
        : "+f"(d[0]), "+f"(d[1]), "+f"(d[2]), "+f"(d[3])
        : "r"(a[0]), "r"(a[1]), "r"(a[2]), "r"(a[3]), "r"(b[0]), "r"(b[1]));
}

// ---------------------------------------------------------------- prep kernel
__global__ void qconv_kernel(const float* __restrict__ qm) {
    int w    = (blockIdx.x * blockDim.x + threadIdx.x) >> 5;
    int lane = threadIdx.x & 31;
    if (w >= B_Q) return;
    const float4* row = (const float4*)(qm + (size_t)w * DIM);
    uint2* dh = (uint2*)g_qhi + (size_t)w * 128;
    float s = 0.f;
#pragma unroll
    for (int j = 0; j < 4; j++) {
        int f = lane + 32 * j;
        float4 v = row[f];
        __nv_bfloat162 h0 = __floats2bfloat162_rn(v.x, v.y);
        __nv_bfloat162 h1 = __floats2bfloat162_rn(v.z, v.w);
        uint2 hu;
        hu.x = ((uint32_t)__bfloat16_as_ushort(h0.y) << 16) | __bfloat16_as_ushort(h0.x);
        hu.y = ((uint32_t)__bfloat16_as_ushort(h1.y) << 16) | __bfloat16_as_ushort(h1.x);
        dh[f] = hu;
        s += v.x * v.x + v.y * v.y + v.z * v.z + v.w * v.w;
    }
#pragma unroll
    for (int o = 16; o > 0; o >>= 1) s += __shfl_xor_sync(0xFFFFFFFFu, s, o);
    if (lane == 0) g_qsq[w] = s;
}

// ---------------------------------------------------------------- main kernel
// 1-term bf16 HMMA: approx d2; keeps top-TILE_K per query per tile.
__global__ void __launch_bounds__(256, 1) knn_hmma(const float* __restrict__ mem) {
    extern __shared__ char smem[];
    const uint32_t sb = smem_u32(smem);
    const int tid  = threadIdx.x;
    const int lane = tid & 31;
    const int wid  = tid >> 5;
    const int wm   = wid >> 1;          // 0..3 : warp m-tile (64 queries)
    const int wn   = wid & 1;           // 0..1 : warp n-tile (64 rows)
    const int n0   = blockIdx.x * BN;

    // ldsm per-lane offsets (pitch 144 = 16*9, 9 mod 8 = 1 -> conflict-free)
    const uint32_t offA = (uint32_t)((wm * 64 + (lane & 15)) * PITCH + ((lane >> 4) << 4));
    const uint32_t offB = (uint32_t)((wn * 64 + (lane & 7) + ((lane >> 4) << 3)) * PITCH
                                     + (((lane >> 3) & 1) << 4));

    float acc[4][8][4];
#pragma unroll
    for (int i = 0; i < 4; i++)
#pragma unroll
        for (int j = 0; j < 8; j++)
#pragma unroll
            for (int r = 0; r < 4; r++) acc[i][j][r] = 0.f;

    float sqa[8];                       // per-thread ||m||^2 partials (8 rows)
#pragma unroll
    for (int i = 0; i < 8; i++) sqa[i] = 0.f;

    // ---- staging helpers ----
    auto stageA = [&](int k) {          // A(k) bf16 -> abuf[k&1]
        uint32_t base = sb + SM_A + (k & 1) * 36864;
#pragma unroll
        for (int i = 0; i < 8; i++) {
            int idx = i * 256 + tid;            // [0,2048)
            int r = idx >> 3, j = idx & 7;
            cp16(base + (uint32_t)(r * PITCH + j * 16),
                 (const char*)g_qhi + (size_t)r * 1024 + (size_t)k * 128 + (size_t)j * 16);
        }
    };
    auto stageB = [&](int k) {          // B(k) fp32 -> fbuf[k&1]
        uint32_t base = sb + SM_BF + (k & 1) * 34816;
#pragma unroll
        for (int i = 0; i < 8; i++) {
            int idx = i * 256 + tid;            // [0,2048)
            int r = idx >> 4, j = idx & 15;
            int grow = n0 + r;
            if (grow >= N_MEM) grow = N_MEM - 1;
            cp16(base + (uint32_t)(r * FPITCH + j * 16),
                 (const char*)(mem + (size_t)grow * DIM) + (size_t)k * 256 + (size_t)j * 16);
        }
    };
    auto convB = [&](int k) {           // fbuf[k&1] fp32 -> bbuf[k&1] bf16, + sq
        const char* f = smem + SM_BF + (k & 1) * 34816;
        char*       b = smem + SM_BB + (k & 1) * 18432;
        const int c16 = tid & 15;
        const int rb  = tid >> 4;
#pragma unroll
        for (int i = 0; i < 8; i++) {
            int r = i * 16 + rb;
            float4 v = *(const float4*)(f + r * FPITCH + c16 * 16);
            __nv_bfloat162 h0 = __floats2bfloat162_rn(v.x, v.y);
            __nv_bfloat162 h1 = __floats2bfloat162_rn(v.z, v.w);
            uint2 hu;
            hu.x = ((uint32_t)__bfloat16_as_ushort(h0.y) << 16) | __bfloat16_as_ushort(h0.x);
            hu.y = ((uint32_t)__bfloat16_as_ushort(h1.y) << 16) | __bfloat16_as_ushort(h1.x);
            *(uint2*)(b + r * PITCH + c16 * 8) = hu;
            sqa[i] += v.x * v.x + v.y * v.y + v.z * v.z + v.w * v.w;
        }
    };

    // ---- prologue ----
    stageA(0); stageB(0); stageB(1); CP_COMMIT();
    CP_WAIT0();
    __syncthreads();
    convB(0);

    // ---- main loop: one sync per KC=64 chunk ----
    for (int c = 0; c < NCH; c++) {
        CP_WAIT0();                 // group committed last iter: A(c), B(c+1)
        __syncthreads();            // everyone past MMA(c-1); staged data visible
        if (c + 1 < NCH) {
            stageA(c + 1);
            if (c + 2 < NCH) stageB(c + 2);
            CP_COMMIT();
            convB(c + 1);           // fp32(c+1) -> bf16 buf[(c+1)&1], overlaps MMA(c)
        }

        uint32_t aB = sb + SM_A  + (c & 1) * 36864;
        uint32_t bB = sb + SM_BB + (c & 1) * 18432;
#pragma unroll
        for (int ks = 0; ks < 4; ks++) {
            const uint32_t ka = ks * 32;
            uint32_t Ah[4][4], Bh[8][2];
#pragma unroll
            for (int mi = 0; mi < 4; mi++)
                ldsm4(aB + mi * 16 * PITCH + offA + ka,
                      Ah[mi][0], Ah[mi][1], Ah[mi][2], Ah[mi][3]);
#pragma unroll
            for (int jp = 0; jp < 4; jp++)
                ldsm4(bB + jp * 16 * PITCH + offB + ka,
                      Bh[jp*2][0], Bh[jp*2][1], Bh[jp*2+1][0], Bh[jp*2+1][1]);
#pragma unroll
            for (int mi = 0; mi < 4; mi++)
#pragma unroll
                for (int ni = 0; ni < 8; ni++)
                    mma_bf16(acc[mi][ni], Ah[mi], Bh[ni]);
        }
    }
    __syncthreads();

    // ---- ||m||^2 reduce (across 16 c16 lanes) ----
    {
        float* msp = (float*)(smem + SM_MS);
#pragma unroll
        for (int i = 0; i < 8; i++) {
            float s = sqa[i];
            s += __shfl_xor_sync(0xFFFFFFFFu, s, 1);
            s += __shfl_xor_sync(0xFFFFFFFFu, s, 2);
            s += __shfl_xor_sync(0xFFFFFFFFu, s, 4);
            s += __shfl_xor_sync(0xFFFFFFFFu, s, 8);
            if ((lane & 15) == 0) msp[i * 16 + (tid >> 4)] = s;
        }
    }

    // ---- epilogue: dot products -> smem dist tile (pitch 129 floats) ----
    float* ds = (float*)smem;
#pragma unroll
    for (int mi = 0; mi < 4; mi++) {
        int m = wm * 64 + mi * 16 + (lane >> 2);
#pragma unroll
        for (int ni = 0; ni < 8; ni++) {
            int n = wn * 64 + ni * 8 + (lane & 3) * 2;
            ds[m * 129 + n]           = acc[mi][ni][0];
            ds[m * 129 + n + 1]       = acc[mi][ni][1];
            ds[(m + 8) * 129 + n]     = acc[mi][ni][2];
            ds[(m + 8) * 129 + n + 1] = acc[mi][ni][3];
        }
    }
    __syncthreads();

    // ---- per-query approx top-TILE_K over this CTA's 128 columns ----
    {
        const float qsq = g_qsq[tid];
        const float* row = ds + tid * 129;
        const float* msp = (const float*)(smem + SM_MS);
        const int nvalid = (n0 + BN <= N_MEM) ? BN : (N_MEM - n0);
        float bd[TILE_K]; int bix[TILE_K];
#pragma unroll
        for (int j = 0; j < TILE_K; j++) { bd[j] = 3.0e38f; bix[j] = 0x7FFFFFFF; }
        for (int n = 0; n < nvalid; n++) {
            float dist = qsq + msp[n] - 2.0f * row[n];
            if (dist < bd[TILE_K - 1]) {
                int p = TILE_K - 1;
                while (p > 0 && bd[p - 1] > dist) {
                    bd[p] = bd[p - 1]; bix[p] = bix[p - 1]; --p;
                }
                bd[p] = dist; bix[p] = n0 + n;
            }
        }
#pragma unroll
        for (int j = 0; j < TILE_K; j++) {
            size_t o = ((size_t)tid * NTILE + blockIdx.x) * TILE_K + j;
            g_pd[o] = bd[j];
            g_pi[o] = bix[j];
        }
    }
}

// ---------------------------------------------------------------- final:
// merge approx partials -> global approx top-GK -> exact fp32 rescore -> top-5
__global__ void __launch_bounds__(512) knn_final(const float* __restrict__ qm,
                                                 const float* __restrict__ mem,
                                                 float* __restrict__ out, int out_elems) {
    const int qy   = blockIdx.x;
    const int tid  = threadIdx.x;
    const int lane = tid & 31;
    const int w    = tid >> 5;
    const int CAND = NTILE * TILE_K;
    const float* pd = g_pd + (size_t)qy * CAND;
    const int*   pi = g_pi + (size_t)qy * CAND;

    __shared__ float swd[16][GK];
    __shared__ int   swi[16][GK];
    __shared__ int   cidx[GK];
    __shared__ float cd2[GK];

    // phase A: per-thread approx top-8
    const int PK = 8;
    float d[PK]; int ix[PK];
#pragma unroll
    for (int j = 0; j < PK; j++) { d[j] = 3.0e38f; ix[j] = 0x7FFFFFFF; }
    for (int c = tid; c < CAND; c += 512) {
        float dv = pd[c];
        if (dv < d[PK - 1]) {
            int di = pi[c];
            int p = PK - 1;
            while (p > 0 && (d[p-1] > dv || (d[p-1] == dv && ix[p-1] > di))) {
                d[p] = d[p-1]; ix[p] = ix[p-1]; --p;
            }
            d[p] = dv; ix[p] = di;
        }
    }

    // per-warp sorted-head merge -> sorted GK per warp
    {
        int p = 0;
#pragma unroll
        for (int r = 0; r < GK; r++) {
            float v = (p < PK) ? d[p] : 3.0e38f;
            int  id = (p < PK) ? ix[p] : 0x7FFFFFFF;
            float bv = v; int bi2 = id;
#pragma unroll
            for (int o = 16; o > 0; o >>= 1) {
                float ov = __shfl_xor_sync(0xFFFFFFFFu, bv, o);
                int   oi = __shfl_xor_sync(0xFFFFFFFFu, bi2, o);
                if (ov < bv || (ov == bv && oi < bi2)) { bv = ov; bi2 = oi; }
            }
            if (p < PK && v == bv && id == bi2) p++;   // unique indices -> unique winner
            if (lane == 0) { swd[w][r] = bv; swi[w][r] = bi2; }
        }
    }
    __syncthreads();

    // thread 0: 16-way merge of sorted lists -> global approx top-GK indices
    if (tid == 0) {
        int hp[16];
#pragma unroll
        for (int i = 0; i < 16; i++) hp[i] = 0;
        for (int r = 0; r < GK; r++) {
            float bv = 3.0e38f; int bi2 = 0x7FFFFFFF, bw = -1;
            for (int i = 0; i < 16; i++) {
                if (hp[i] < GK) {
                    float v = swd[i][hp[i]]; int id = swi[i][hp[i]];
                    if (v < bv || (v == bv && id < bi2)) { bv = v; bi2 = id; bw = i; }
                }
            }
            hp[bw]++;
            cidx[r] = bi2;
        }
    }
    __syncthreads();

    // phase B: exact fp32 rescore of GK candidates (one warp per candidate)
    const float qsq = g_qsq[qy];
    const float4* qrow = (const float4*)(qm + (size_t)qy * DIM);
    for (int cc = w; cc < GK; cc += 16) {
        int row = cidx[cc];
        float dot = 0.f, ms = 0.f;
        if (row < N_MEM) {
            const float4* mrow = (const float4*)(mem + (size_t)row * DIM);
#pragma unroll
            for (int j = 0; j < 4; j++) {
                float4 qv = qrow[lane + 32 * j];
                float4 mv = mrow[lane + 32 * j];
                dot += qv.x * mv.x + qv.y * mv.y + qv.z * mv.z + qv.w * mv.w;
                ms  += mv.x * mv.x + mv.y * mv.y + mv.z * mv.z + mv.w * mv.w;
            }
        }
#pragma unroll
        for (int o = 16; o > 0; o >>= 1) {
            dot += __shfl_xor_sync(0xFFFFFFFFu, dot, o);
            ms  += __shfl_xor_sync(0xFFFFFFFFu, ms, o);
        }
        if (lane == 0)
            cd2[cc] = (row < N_MEM) ? (qsq + ms - 2.0f * dot) : 3.0e38f;
    }
    __syncthreads();

    // thread 0: exact top-5 of the GK candidates
    if (tid == 0) {
        float fd[TOPK]; int fi[TOPK];
#pragma unroll
        for (int j = 0; j < TOPK; j++) { fd[j] = 3.0e38f; fi[j] = 0x7FFFFFFF; }
        for (int c = 0; c < GK; c++) {
            float dv = cd2[c]; int di = cidx[c];
            if (dv < fd[TOPK-1] || (dv == fd[TOPK-1] && di < fi[TOPK-1])) {
                int p = TOPK - 1;
                while (p > 0 && (fd[p-1] > dv || (fd[p-1] == dv && fi[p-1] > di))) {
                    fd[p] = fd[p-1]; fi[p] = fi[p-1]; --p;
                }
                fd[p] = dv; fi[p] = di;
            }
        }
#pragma unroll
        for (int j = 0; j < TOPK; j++) {
            out[qy * TOPK + j] = fd[j];
            if (out_elems >= 2 * B_Q * TOPK)
                out[B_Q * TOPK + qy * TOPK + j] = (float)fi[j];
        }
    }
}

// ---------------------------------------------------------------- launch
extern "C" void kernel_launch(void* const* d_in, const int* in_sizes, int n_in,
                              void* d_out, int out_size) {
    const float* qm  = (const float*)d_in[0];   // query  [256, 512] f32
    const float* mem = (const float*)d_in[1];   // memory [500000, 512] f32
    (void)in_sizes; (void)n_in;

    cudaFuncSetAttribute(knn_hmma, cudaFuncAttributeMaxDynamicSharedMemorySize, SMEM_BYTES);

    qconv_kernel<<<B_Q / 8, 256>>>(qm);
    knn_hmma<<<NTILE, 256, SMEM_BYTES>>>(mem);
    knn_final<<<B_Q, 512>>>(qm, mem, (float*)d_out, out_size);
}